// round 1
// baseline (speedup 1.0000x reference)
#include <cuda_runtime.h>
#include <cstdint>
#include <cstddef>

#define N_NODES 4096
#define HID     256
#define NHEAD   8
#define DHEAD   32
#define EPS_BN  1e-5f

// ---------------- scratch (single __device__ array, no allocations) ----------------
#define OFF_Q    0u
#define OFF_K    (1u<<20)
#define OFF_V    (2u<<20)
#define OFF_O    (3u<<20)
#define OFF_X1   (4u<<20)
#define OFF_H2   (5u<<20)
#define OFF_Y2   (6u<<20)
#define OFF_Y1   (7u<<20)            /* 2M floats */
#define OFF_PS   (9u<<20)
#define OFF_PQ   (OFF_PS + 16384u)
#define OFF_MEAN (OFF_PQ + 16384u)
#define OFF_INV  (OFF_MEAN + 256u)
#define SCRATCH_FLOATS (OFF_INV + 256u)

__device__ float g_scratch[SCRATCH_FLOATS];

// ---------------- tiled GEMM: out[M,N] = X[M,KD] @ W[N,KD]^T (+epilogue) -----------
// EPI 0: (acc+bias)*scale    (QKV; q uses scale=1/sqrt(32))
// EPI 1: relu(acc+bias)      (W1)
// EPI 2: acc+bias+res        (Wo + residual h, W2 + residual h2)
template<int KD, int EPI>
__global__ __launch_bounds__(256) void gemm64(const float* __restrict__ X,
                                              const float* __restrict__ W,
                                              const float* __restrict__ bias,
                                              const float* __restrict__ res,
                                              float* __restrict__ out,
                                              int nout, float scale)
{
    __shared__ float Xs[16][68];
    __shared__ float Ws[16][68];
    const int tid = threadIdx.x;
    const int tx = tid & 15, ty = tid >> 4;
    const int mBase = blockIdx.x * 64, nBase = blockIdx.y * 64;
    const int lr = tid >> 2;            // tile row 0..63
    const int lk = (tid & 3) << 2;      // k offset 0,4,8,12

    float acc[4][4];
#pragma unroll
    for (int i = 0; i < 4; i++)
#pragma unroll
        for (int j = 0; j < 4; j++) acc[i][j] = 0.f;

    for (int k0 = 0; k0 < KD; k0 += 16) {
        float4 xv = *(const float4*)(X + (size_t)(mBase + lr) * KD + k0 + lk);
        float4 wv = *(const float4*)(W + (size_t)(nBase + lr) * KD + k0 + lk);
        if (k0) __syncthreads();
        Xs[lk + 0][lr] = xv.x; Xs[lk + 1][lr] = xv.y; Xs[lk + 2][lr] = xv.z; Xs[lk + 3][lr] = xv.w;
        Ws[lk + 0][lr] = wv.x; Ws[lk + 1][lr] = wv.y; Ws[lk + 2][lr] = wv.z; Ws[lk + 3][lr] = wv.w;
        __syncthreads();
#pragma unroll
        for (int k = 0; k < 16; k++) {
            float4 a4 = *(const float4*)&Xs[k][ty << 2];
            float4 b4 = *(const float4*)&Ws[k][tx << 2];
            float av[4] = {a4.x, a4.y, a4.z, a4.w};
            float bv[4] = {b4.x, b4.y, b4.z, b4.w};
#pragma unroll
            for (int i = 0; i < 4; i++)
#pragma unroll
                for (int j = 0; j < 4; j++) acc[i][j] += av[i] * bv[j];
        }
    }

    float4 bb = *(const float4*)(bias + nBase + (tx << 2));
    float bvv[4] = {bb.x, bb.y, bb.z, bb.w};
#pragma unroll
    for (int i = 0; i < 4; i++) {
        const int row = mBase + (ty << 2) + i;
        float o[4];
#pragma unroll
        for (int j = 0; j < 4; j++) o[j] = acc[i][j] + bvv[j];
        if (EPI == 0) {
#pragma unroll
            for (int j = 0; j < 4; j++) o[j] *= scale;
        }
        if (EPI == 1) {
#pragma unroll
            for (int j = 0; j < 4; j++) o[j] = fmaxf(o[j], 0.f);
        }
        if (EPI == 2) {
            float4 rv = *(const float4*)(res + (size_t)row * nout + nBase + (tx << 2));
            o[0] += rv.x; o[1] += rv.y; o[2] += rv.z; o[3] += rv.w;
        }
        *(float4*)(out + (size_t)row * nout + nBase + (tx << 2)) =
            make_float4(o[0], o[1], o[2], o[3]);
    }
}

// ---------------- fused flash attention with multiplicative adjacency mask --------
// Per block: one head, 64 query rows. S = Q·K^T (Q pre-scaled), logits = S*A,
// online softmax across 64 key tiles, O = P·V, normalized at the end.
__global__ __launch_bounds__(256, 2) void flash_attn(const float* __restrict__ A,
                                                     const float* __restrict__ Q,
                                                     const float* __restrict__ K,
                                                     const float* __restrict__ V,
                                                     float* __restrict__ O)
{
    __shared__ float Qt[32][68];   // k-major
    __shared__ float Kt[32][68];   // k-major
    __shared__ float Vs[64][36];   // row-major
    __shared__ float Ps[64][68];
    __shared__ float fac_s[64];
    __shared__ float l_s[64];

    const int tid = threadIdx.x;
    const int tx = tid & 15, ty = tid >> 4;   // S-phase mapping: rows 4*ty.., cols 4*tx..
    const int dx = tid & 7,  ry = tid >> 3;   // PV mapping: rows 2*ry.., d cols 4*dx..
    const int head  = blockIdx.y;
    const int rBase = blockIdx.x * 64;
    const float* Qh = Q + (size_t)head * (N_NODES * DHEAD);
    const float* Kh = K + (size_t)head * (N_NODES * DHEAD);
    const float* Vh = V + (size_t)head * (N_NODES * DHEAD);
    float*       Oh = O + (size_t)head * (N_NODES * DHEAD);

    // load Q tile transposed into smem
#pragma unroll
    for (int p = 0; p < 2; p++) {
        int f = tid + (p << 8);
        int r = f >> 3, kk = (f & 7) << 2;
        float4 v = *(const float4*)(Qh + (size_t)(rBase + r) * DHEAD + kk);
        Qt[kk + 0][r] = v.x; Qt[kk + 1][r] = v.y; Qt[kk + 2][r] = v.z; Qt[kk + 3][r] = v.w;
    }

    float m_i[4], l_i[4];
#pragma unroll
    for (int i = 0; i < 4; i++) { m_i[i] = -1e30f; l_i[i] = 0.f; }
    float acc[2][4];
#pragma unroll
    for (int i = 0; i < 2; i++)
#pragma unroll
        for (int j = 0; j < 4; j++) acc[i][j] = 0.f;

    // prefetch K/V tile 0 into registers
    float4 kreg[2], vreg[2];
#pragma unroll
    for (int p = 0; p < 2; p++) {
        int f = tid + (p << 8);
        int r = f >> 3, kk = (f & 7) << 2;
        kreg[p] = *(const float4*)(Kh + (size_t)r * DHEAD + kk);
        vreg[p] = *(const float4*)(Vh + (size_t)r * DHEAD + kk);
    }

    for (int step = 0; step < 64; step++) {
        // commit prefetched K (transposed) and V (row-major) to smem
#pragma unroll
        for (int p = 0; p < 2; p++) {
            int f = tid + (p << 8);
            int r = f >> 3, kk = (f & 7) << 2;
            Kt[kk + 0][r] = kreg[p].x; Kt[kk + 1][r] = kreg[p].y;
            Kt[kk + 2][r] = kreg[p].z; Kt[kk + 3][r] = kreg[p].w;
            *(float4*)&Vs[r][kk] = vreg[p];
        }
        __syncthreads();

        const int mBase = step << 6;
        // adjacency tile for this step (consumed after the S loop -> latency covered)
        float4 a4[4];
#pragma unroll
        for (int i = 0; i < 4; i++)
            a4[i] = *(const float4*)(A + (size_t)(rBase + (ty << 2) + i) * N_NODES
                                       + mBase + (tx << 2));
        // prefetch next K/V tile
        if (step < 63) {
            const int nb = mBase + 64;
#pragma unroll
            for (int p = 0; p < 2; p++) {
                int f = tid + (p << 8);
                int r = f >> 3, kk = (f & 7) << 2;
                kreg[p] = *(const float4*)(Kh + (size_t)(nb + r) * DHEAD + kk);
                vreg[p] = *(const float4*)(Vh + (size_t)(nb + r) * DHEAD + kk);
            }
        }

        // S = Q K^T
        float S[4][4];
#pragma unroll
        for (int i = 0; i < 4; i++)
#pragma unroll
            for (int j = 0; j < 4; j++) S[i][j] = 0.f;
#pragma unroll 8
        for (int k = 0; k < 32; k++) {
            float4 q4 = *(const float4*)&Qt[k][ty << 2];
            float4 k4 = *(const float4*)&Kt[k][tx << 2];
            float qa[4] = {q4.x, q4.y, q4.z, q4.w};
            float ka[4] = {k4.x, k4.y, k4.z, k4.w};
#pragma unroll
            for (int i = 0; i < 4; i++)
#pragma unroll
                for (int j = 0; j < 4; j++) S[i][j] += qa[i] * ka[j];
        }

        // logits = S * A; online softmax per row (reduce over the 16 tx lanes)
        float fac[4];
#pragma unroll
        for (int i = 0; i < 4; i++) {
            float af[4] = {a4[i].x, a4[i].y, a4[i].z, a4[i].w};
#pragma unroll
            for (int j = 0; j < 4; j++) S[i][j] *= af[j];
            float rm = fmaxf(fmaxf(S[i][0], S[i][1]), fmaxf(S[i][2], S[i][3]));
#pragma unroll
            for (int o = 8; o >= 1; o >>= 1)
                rm = fmaxf(rm, __shfl_xor_sync(0xffffffffu, rm, o, 16));
            const float mn = fmaxf(m_i[i], rm);
            fac[i] = __expf(m_i[i] - mn);
            float rs = 0.f;
#pragma unroll
            for (int j = 0; j < 4; j++) {
                float p = __expf(S[i][j] - mn);
                S[i][j] = p; rs += p;
            }
#pragma unroll
            for (int o = 8; o >= 1; o >>= 1)
                rs += __shfl_xor_sync(0xffffffffu, rs, o, 16);
            l_i[i] = l_i[i] * fac[i] + rs;
            m_i[i] = mn;
            *(float4*)&Ps[(ty << 2) + i][tx << 2] = make_float4(S[i][0], S[i][1], S[i][2], S[i][3]);
        }
        if (tx == 0) {
#pragma unroll
            for (int i = 0; i < 4; i++) fac_s[(ty << 2) + i] = fac[i];
        }
        __syncthreads();

        // O = O*fac + P V
        {
            const int r0 = ry << 1;
            const float sc0 = fac_s[r0], sc1 = fac_s[r0 + 1];
#pragma unroll
            for (int j = 0; j < 4; j++) { acc[0][j] *= sc0; acc[1][j] *= sc1; }
#pragma unroll 8
            for (int m = 0; m < 64; m++) {
                float4 v4 = *(const float4*)&Vs[m][dx << 2];
                float p0 = Ps[r0][m], p1 = Ps[r0 + 1][m];
                acc[0][0] += p0 * v4.x; acc[0][1] += p0 * v4.y;
                acc[0][2] += p0 * v4.z; acc[0][3] += p0 * v4.w;
                acc[1][0] += p1 * v4.x; acc[1][1] += p1 * v4.y;
                acc[1][2] += p1 * v4.z; acc[1][3] += p1 * v4.w;
            }
        }
        __syncthreads();
    }

    if (tx == 0) {
#pragma unroll
        for (int i = 0; i < 4; i++) l_s[(ty << 2) + i] = l_i[i];
    }
    __syncthreads();
    {
        const int r0 = ry << 1;
        const float inv0 = 1.f / l_s[r0];
        const float inv1 = 1.f / l_s[r0 + 1];
        *(float4*)(Oh + (size_t)(rBase + r0) * DHEAD + (dx << 2)) =
            make_float4(acc[0][0] * inv0, acc[0][1] * inv0, acc[0][2] * inv0, acc[0][3] * inv0);
        *(float4*)(Oh + (size_t)(rBase + r0 + 1) * DHEAD + (dx << 2)) =
            make_float4(acc[1][0] * inv1, acc[1][1] * inv1, acc[1][2] * inv1, acc[1][3] * inv1);
    }
}

// ---------------- deterministic two-stage BatchNorm ----------------
__global__ void bn_partial(const float* __restrict__ x,
                           float* __restrict__ ps, float* __restrict__ pq)
{
    const int t = threadIdx.x;
    const float* p = x + (size_t)blockIdx.x * 64 * HID + t;
    float s = 0.f, q = 0.f;
#pragma unroll 8
    for (int r = 0; r < 64; r++) { float v = p[(size_t)r * HID]; s += v; q += v * v; }
    ps[blockIdx.x * HID + t] = s;
    pq[blockIdx.x * HID + t] = q;
}

__global__ void bn_finalize(const float* __restrict__ ps, const float* __restrict__ pq,
                            float* __restrict__ mean, float* __restrict__ inv)
{
    const int t = threadIdx.x;
    float s = 0.f, q = 0.f;
#pragma unroll 8
    for (int b = 0; b < 64; b++) { s += ps[b * HID + t]; q += pq[b * HID + t]; }
    const float m   = s * (1.f / (float)N_NODES);
    const float var = q * (1.f / (float)N_NODES) - m * m;
    mean[t] = m;
    inv[t]  = rsqrtf(var + EPS_BN);
}

__global__ void bn_apply(const float* __restrict__ x, const float* __restrict__ mean,
                         const float* __restrict__ inv, const float* __restrict__ g,
                         const float* __restrict__ be, float* __restrict__ out)
{
    const int idx = blockIdx.x * blockDim.x + threadIdx.x;  // float4 index
    const int c4 = (idx & 63) << 2;
    float4 v  = *(const float4*)(x + (size_t)idx * 4);
    float4 mm = *(const float4*)(mean + c4);
    float4 iv = *(const float4*)(inv + c4);
    float4 gg = *(const float4*)(g + c4);
    float4 bb = *(const float4*)(be + c4);
    float4 o;
    o.x = (v.x - mm.x) * iv.x * gg.x + bb.x;
    o.y = (v.y - mm.y) * iv.y * gg.y + bb.y;
    o.z = (v.z - mm.z) * iv.z * gg.z + bb.z;
    o.w = (v.w - mm.w) * iv.w * gg.w + bb.w;
    *(float4*)(out + (size_t)idx * 4) = o;
}

// ---------------- launch ----------------
extern "C" void kernel_launch(void* const* d_in, const int* in_sizes, int n_in,
                              void* d_out, int out_size)
{
    (void)in_sizes; (void)n_in; (void)out_size;
    const float* A   = (const float*)d_in[0];
    const float* h   = (const float*)d_in[1];
    const float* Wq  = (const float*)d_in[2];
    const float* bq  = (const float*)d_in[3];
    const float* Wk  = (const float*)d_in[4];
    const float* bk  = (const float*)d_in[5];
    const float* Wv  = (const float*)d_in[6];
    const float* bv  = (const float*)d_in[7];
    const float* Wo  = (const float*)d_in[8];
    const float* bo  = (const float*)d_in[9];
    const float* W1  = (const float*)d_in[10];
    const float* c1  = (const float*)d_in[11];
    const float* W2  = (const float*)d_in[12];
    const float* c2  = (const float*)d_in[13];
    const float* g1  = (const float*)d_in[14];
    const float* be1 = (const float*)d_in[15];
    const float* g2  = (const float*)d_in[16];
    const float* be2 = (const float*)d_in[17];
    float* out = (float*)d_out;

    float* S = nullptr;
    cudaGetSymbolAddress((void**)&S, g_scratch);
    float* Qb  = S + OFF_Q;
    float* Kb  = S + OFF_K;
    float* Vb  = S + OFF_V;
    float* Ob  = S + OFF_O;
    float* X1  = S + OFF_X1;
    float* H2  = S + OFF_H2;
    float* Y2  = S + OFF_Y2;
    float* Y1  = S + OFF_Y1;
    float* PS  = S + OFF_PS;
    float* PQ  = S + OFF_PQ;
    float* MEAN= S + OFF_MEAN;
    float* INV = S + OFF_INV;

    const float qscale = 0.17677669529663687f;  // 32^-0.5
    dim3 g64x4(64, 4), g64x8(64, 8), gfa(64, NHEAD);

    // QKV projections (q pre-scaled)
    gemm64<256, 0><<<g64x4, 256>>>(h, Wq, bq, nullptr, Qb, HID, qscale);
    gemm64<256, 0><<<g64x4, 256>>>(h, Wk, bk, nullptr, Kb, HID, 1.f);
    gemm64<256, 0><<<g64x4, 256>>>(h, Wv, bv, nullptr, Vb, HID, 1.f);
    // fused masked attention
    flash_attn<<<gfa, 256>>>(A, Qb, Kb, Vb, Ob);
    // output projection + residual h
    gemm64<256, 2><<<g64x4, 256>>>(Ob, Wo, bo, h, X1, HID, 1.f);
    // BatchNorm 1
    bn_partial<<<64, 256>>>(X1, PS, PQ);
    bn_finalize<<<1, 256>>>(PS, PQ, MEAN, INV);
    bn_apply<<<1024, 256>>>(X1, MEAN, INV, g1, be1, H2);
    // FFN
    gemm64<256, 1><<<g64x8, 256>>>(H2, W1, c1, nullptr, Y1, 2 * HID, 1.f);
    gemm64<512, 2><<<g64x4, 256>>>(Y1, W2, c2, H2, Y2, HID, 1.f);
    // BatchNorm 2 -> output
    bn_partial<<<64, 256>>>(Y2, PS, PQ);
    bn_finalize<<<1, 256>>>(PS, PQ, MEAN, INV);
    bn_apply<<<1024, 256>>>(Y2, MEAN, INV, g2, be2, out);
}